// round 9
// baseline (speedup 1.0000x reference)
#include <cuda_runtime.h>
#include <cstdint>

#define S_SEG 8
#define U_CH 128
#define SU 1024                 // S_SEG * U_CH
#define P_MAX 64
#define GROUPS 4                // z-streams per block (128 threads each)
#define NTHREADS 512
#define TILE_FLOATS (3 * S_SEG * U_CH)   // 3072 floats = 12 KB
#define GRID_BLOCKS 296         // 2 per SM

// All prep outputs in ONE struct -> ONE graph memcpy node per launch.
// j-groups are partitioned 4 ways (one quarter per warp of a group).
struct PrepData {
    uint4 meta[P_MAX];           // {off0,off1,off2 (bytes), coeff_bits}, grouped by (quarter, j)
    int   qnj[4];                // #j-groups per quarter
    int   qjoff[4][S_SEG];       // output byte offset (j * U_CH * 4) per group
    int   qstart[4][S_SEG + 1];  // path-range per group
};

__device__   PrepData g_prep;
__constant__ PrepData c_prep;

__global__ void prep_kernel(const int* __restrict__ path_indices,
                            const float* __restrict__ path_coeff,
                            int P) {
    __shared__ int   sidx[P_MAX * 4];
    __shared__ float scf[P_MAX];
    const int t = threadIdx.x;
    for (int i = t; i < P * 4; i += 32) sidx[i] = path_indices[i];
    for (int i = t; i < P; i += 32) scf[i] = path_coeff[i];
    __syncwarp();
    if (t != 0) return;

    // Count paths per output segment.
    int cnt[S_SEG];
#pragma unroll
    for (int j = 0; j < S_SEG; j++) cnt[j] = 0;
    for (int p = 0; p < P; p++) cnt[sidx[p * 4 + 3]]++;

    // Sort j by count desc; greedy-assign to the lightest of 4 quarters.
    int ord[S_SEG];
#pragma unroll
    for (int j = 0; j < S_SEG; j++) ord[j] = j;
#pragma unroll
    for (int a = 0; a < S_SEG; a++)
#pragma unroll
        for (int b = a + 1; b < S_SEG; b++)
            if (cnt[ord[b]] > cnt[ord[a]]) { int tmp = ord[a]; ord[a] = ord[b]; ord[b] = tmp; }
    int qsum[4] = {0, 0, 0, 0};
    int qnj[4] = {0, 0, 0, 0};
    int qj[4][S_SEG];
#pragma unroll
    for (int a = 0; a < S_SEG; a++) {
        int q = 0;
        for (int b = 1; b < 4; b++) if (qsum[b] < qsum[q]) q = b;
        qj[q][qnj[q]++] = ord[a];
        qsum[q] += cnt[ord[a]];
    }

    // Emission-order bases per j; group descriptors.
    int base[S_SEG];
    int pos = 0;
    for (int q = 0; q < 4; q++) {
        g_prep.qnj[q] = qnj[q];
        g_prep.qstart[q][0] = pos;
        for (int tt = 0; tt < qnj[q]; tt++) {
            int j = qj[q][tt];
            g_prep.qjoff[q][tt] = j * U_CH * 4;
            g_prep.qstart[q][tt] = pos;
            base[j] = pos;
            pos += cnt[j];
            g_prep.qstart[q][tt + 1] = pos;
        }
        for (int tt = qnj[q]; tt < S_SEG; tt++) {
            g_prep.qjoff[q][tt] = 0;
            g_prep.qstart[q][tt + 1] = pos;
        }
    }

    // Single placement pass (deterministic order within each j).
    for (int p = 0; p < P; p++) {
        int i0 = sidx[p * 4 + 0];
        int i1 = sidx[p * 4 + 1];
        int i2 = sidx[p * 4 + 2];
        int j  = sidx[p * 4 + 3];
        uint4 m;
        m.x = (unsigned)((0 * S_SEG + i0) * U_CH * 4);
        m.y = (unsigned)((1 * S_SEG + i1) * U_CH * 4);
        m.z = (unsigned)((2 * S_SEG + i2) * U_CH * 4);
        m.w = __float_as_uint(scf[p]);
        g_prep.meta[base[j]++] = m;
    }
}

__device__ __forceinline__ unsigned smem_u32(const void* p) {
    unsigned a;
    asm("{ .reg .u64 t; cvta.to.shared.u64 t, %1; cvt.u32.u64 %0, t; }"
        : "=r"(a) : "l"(p));
    return a;
}

__device__ __forceinline__ void lds128(unsigned long long& v0, unsigned long long& v1,
                                       unsigned addr) {
    asm volatile("ld.shared.v2.u64 {%0, %1}, [%2];" : "=l"(v0), "=l"(v1) : "r"(addr));
}

__device__ __forceinline__ unsigned long long mul2(unsigned long long a, unsigned long long b) {
    unsigned long long r;
    asm("mul.rn.f32x2 %0, %1, %2;" : "=l"(r) : "l"(a), "l"(b));
    return r;
}

__device__ __forceinline__ unsigned long long fma2(unsigned long long a, unsigned long long b,
                                                   unsigned long long c) {
    unsigned long long r;
    asm("fma.rn.f32x2 %0, %1, %2, %3;" : "=l"(r) : "l"(a), "l"(b), "l"(c));
    return r;
}

__device__ __forceinline__ unsigned long long add2(unsigned long long a, unsigned long long b) {
    unsigned long long r;
    asm("add.rn.f32x2 %0, %1, %2;" : "=l"(r) : "l"(a), "l"(b));
    return r;
}

__device__ __forceinline__ void cp16(unsigned saddr, const void* gaddr) {
    asm volatile("cp.async.cg.shared.global [%0], [%1], 16;" :: "r"(saddr), "l"(gaddr));
}

__device__ __forceinline__ void cp_commit() {
    asm volatile("cp.async.commit_group;" ::: "memory");
}

template <int N>
__device__ __forceinline__ void cp_wait() {
    asm volatile("cp.async.wait_group %0;" :: "n"(N) : "memory");
}

__device__ __forceinline__ void group_bar(int gid) {
    asm volatile("bar.sync %0, %1;" :: "r"(gid + 1), "r"(128) : "memory");
}

// Stage one z-tile (12 KB) via cp.async: 128 threads x 6 x 16B.
__device__ __forceinline__ void issue_stage(unsigned sdst, long z, int gt,
                                            const float* __restrict__ x0,
                                            const float* __restrict__ x1,
                                            const float* __restrict__ x2) {
    const float* srcs[3] = {x0, x1, x2};
#pragma unroll
    for (int it = 0; it < 6; it++) {
        const int f = it * 128 + gt;          // chunk index (16 B each)
        const int row = f >> 5;
        const int col = f & 31;
        const float* gp = srcs[it >> 1] + z * SU + (row & 7) * U_CH + col * 4;
        cp16(sdst + (unsigned)f * 16, gp);
    }
}

// One path over 4 channels (lane's float4): 3x LDS.128 + packed f32x2 math.
__device__ __forceinline__ void do_path4(unsigned long long& accA, unsigned long long& accB,
                                         unsigned sbase, uint4 m) {
    unsigned long long a0, a1, b0, b1, c0, c1;
    lds128(a0, a1, sbase + m.x);
    lds128(b0, b1, sbase + m.y);
    lds128(c0, c1, sbase + m.z);
    unsigned long long cc;
    asm("mov.b64 %0, {%1, %1};" : "=l"(cc) : "r"(m.w));
    unsigned long long t0 = mul2(a0, b0);
    unsigned long long t1 = mul2(a1, b1);
    t0 = mul2(t0, c0);
    t1 = mul2(t1, c1);
    accA = fma2(t0, cc, accA);
    accB = fma2(t1, cc, accB);
}

__global__ __launch_bounds__(NTHREADS, 2)
void ftp4_kernel(const float* __restrict__ x0,
                 const float* __restrict__ x1,
                 const float* __restrict__ x2,
                 float* __restrict__ out,
                 int Z) {
    extern __shared__ float smem[];   // [GROUPS][2][TILE_FLOATS]

    const int tid = threadIdx.x;
    const int ws = tid >> 5;          // warp slot 0..15
    const int g = ws >> 2;            // group / z-stream 0..3
    const int q = ws & 3;             // j-quarter for this warp
    const int lane = tid & 31;
    const int gt = tid & 127;

    float* buf0 = smem + g * (2 * TILE_FLOATS);
    const unsigned sb0 = smem_u32(buf0);
    const unsigned sb1 = sb0 + TILE_FLOATS * 4;

    const int stream = blockIdx.x * GROUPS + g;
    const int stride = GRID_BLOCKS * GROUPS;            // 1184
    const int nz = (Z > stream) ? ((Z - 1 - stream) / stride + 1) : 0;
    if (nz == 0) return;

    issue_stage(sb0, (long)stream, gt, x0, x1, x2);
    cp_commit();

    const int nj = c_prep.qnj[q];

    for (int k = 0; k < nz; k++) {
        const long z = (long)stream + (long)k * stride;
        const unsigned scur = (k & 1) ? sb1 : sb0;
        const unsigned snxt = (k & 1) ? sb0 : sb1;

        if (k + 1 < nz) {
            issue_stage(snxt, z + stride, gt, x0, x1, x2);
            cp_commit();
            cp_wait<1>();
        } else {
            cp_wait<0>();
        }
        group_bar(g);   // stage k visible to all 4 warps

        // This warp: its quarter's j-groups over ALL 128 channels; lane owns 4.
        const unsigned sbase = scur + (unsigned)(lane * 16);
        char* ozb = (char*)(out + z * SU + lane * 4);

        for (int t = 0; t < nj; t++) {
            const int joff = c_prep.qjoff[q][t];
            const int pb = c_prep.qstart[q][t];
            const int pe = c_prep.qstart[q][t + 1];
            unsigned long long a0A = 0ull, a0B = 0ull, a1A = 0ull, a1B = 0ull;
            int p = pb;
            for (; p + 1 < pe; p += 2) {
                do_path4(a0A, a0B, sbase, c_prep.meta[p]);
                do_path4(a1A, a1B, sbase, c_prep.meta[p + 1]);
            }
            if (p < pe) do_path4(a0A, a0B, sbase, c_prep.meta[p]);
            unsigned long long accA = add2(a0A, a1A);
            unsigned long long accB = add2(a0B, a1B);

            unsigned r0, r1, r2, r3;
            asm("mov.b64 {%0, %1}, %2;" : "=r"(r0), "=r"(r1) : "l"(accA));
            asm("mov.b64 {%0, %1}, %2;" : "=r"(r2), "=r"(r3) : "l"(accB));
            float4 r;
            r.x = __uint_as_float(r0);
            r.y = __uint_as_float(r1);
            r.z = __uint_as_float(r2);
            r.w = __uint_as_float(r3);
            *(float4*)(ozb + joff) = r;
        }

        group_bar(g);   // all readers done before buffer reuse
    }
}

extern "C" void kernel_launch(void* const* d_in, const int* in_sizes, int n_in,
                              void* d_out, int out_size) {
    const float* x0 = (const float*)d_in[0];
    const float* x1 = (const float*)d_in[1];
    const float* x2 = (const float*)d_in[2];
    const float* coeff = (const float*)d_in[3];
    const int*   pidx = (const int*)d_in[4];
    float* out = (float*)d_out;

    const int P = in_sizes[3];            // 64
    const int Z = in_sizes[0] / SU;       // 20000

    prep_kernel<<<1, 32>>>(pidx, coeff, P);

    void* gaddr = nullptr;
    cudaGetSymbolAddress(&gaddr, g_prep);
    cudaMemcpyToSymbolAsync(c_prep, gaddr, sizeof(PrepData), 0,
                            cudaMemcpyDeviceToDevice, 0);

    const size_t smem_bytes = (size_t)GROUPS * 2 * TILE_FLOATS * sizeof(float); // 96 KB

    static bool attr_set = false;
    if (!attr_set) {
        cudaFuncSetAttribute(ftp4_kernel,
                             cudaFuncAttributeMaxDynamicSharedMemorySize,
                             (int)smem_bytes);
        attr_set = true;
    }

    ftp4_kernel<<<GRID_BLOCKS, NTHREADS, smem_bytes>>>(x0, x1, x2, out, Z);
}

// round 10
// speedup vs baseline: 1.0397x; 1.0397x over previous
#include <cuda_runtime.h>
#include <cstdint>

#define S_SEG 8
#define U_CH 128
#define SU 1024                 // S_SEG * U_CH
#define P_MAX 64
#define GROUPS 4                // z-streams per block (128 threads each)
#define NTHREADS 512
#define TILE_FLOATS (3 * S_SEG * U_CH)   // 3072 floats = 12 KB
#define TILE_BYTES (TILE_FLOATS * 4)     // 12288
#define GRID_BLOCKS 296         // 2 per SM

// All prep outputs in ONE struct -> ONE graph memcpy node per launch.
// j-groups are partitioned 4 ways (one quarter per warp of a group).
struct PrepData {
    uint4 meta[P_MAX];           // {off0,off1,off2 (bytes), coeff_bits}, grouped by (quarter, j)
    int   qnj[4];                // #j-groups per quarter
    int   qjoff[4][S_SEG];       // output byte offset (j * U_CH * 4) per group
    int   qstart[4][S_SEG + 1];  // path-range per group
};

__device__   PrepData g_prep;
__constant__ PrepData c_prep;

__global__ void prep_kernel(const int* __restrict__ path_indices,
                            const float* __restrict__ path_coeff,
                            int P) {
    __shared__ int   sidx[P_MAX * 4];
    __shared__ float scf[P_MAX];
    const int t = threadIdx.x;
    for (int i = t; i < P * 4; i += 32) sidx[i] = path_indices[i];
    for (int i = t; i < P; i += 32) scf[i] = path_coeff[i];
    __syncwarp();
    if (t != 0) return;

    int cnt[S_SEG];
#pragma unroll
    for (int j = 0; j < S_SEG; j++) cnt[j] = 0;
    for (int p = 0; p < P; p++) cnt[sidx[p * 4 + 3]]++;

    int ord[S_SEG];
#pragma unroll
    for (int j = 0; j < S_SEG; j++) ord[j] = j;
#pragma unroll
    for (int a = 0; a < S_SEG; a++)
#pragma unroll
        for (int b = a + 1; b < S_SEG; b++)
            if (cnt[ord[b]] > cnt[ord[a]]) { int tmp = ord[a]; ord[a] = ord[b]; ord[b] = tmp; }
    int qsum[4] = {0, 0, 0, 0};
    int qnj[4] = {0, 0, 0, 0};
    int qj[4][S_SEG];
#pragma unroll
    for (int a = 0; a < S_SEG; a++) {
        int q = 0;
        for (int b = 1; b < 4; b++) if (qsum[b] < qsum[q]) q = b;
        qj[q][qnj[q]++] = ord[a];
        qsum[q] += cnt[ord[a]];
    }

    int base[S_SEG];
    int pos = 0;
    for (int q = 0; q < 4; q++) {
        g_prep.qnj[q] = qnj[q];
        g_prep.qstart[q][0] = pos;
        for (int tt = 0; tt < qnj[q]; tt++) {
            int j = qj[q][tt];
            g_prep.qjoff[q][tt] = j * U_CH * 4;
            g_prep.qstart[q][tt] = pos;
            base[j] = pos;
            pos += cnt[j];
            g_prep.qstart[q][tt + 1] = pos;
        }
        for (int tt = qnj[q]; tt < S_SEG; tt++) {
            g_prep.qjoff[q][tt] = 0;
            g_prep.qstart[q][tt + 1] = pos;
        }
    }

    for (int p = 0; p < P; p++) {
        int i0 = sidx[p * 4 + 0];
        int i1 = sidx[p * 4 + 1];
        int i2 = sidx[p * 4 + 2];
        int j  = sidx[p * 4 + 3];
        uint4 m;
        m.x = (unsigned)((0 * S_SEG + i0) * U_CH * 4);
        m.y = (unsigned)((1 * S_SEG + i1) * U_CH * 4);
        m.z = (unsigned)((2 * S_SEG + i2) * U_CH * 4);
        m.w = __float_as_uint(scf[p]);
        g_prep.meta[base[j]++] = m;
    }
}

__device__ __forceinline__ unsigned smem_u32(const void* p) {
    unsigned a;
    asm("{ .reg .u64 t; cvta.to.shared.u64 t, %1; cvt.u32.u64 %0, t; }"
        : "=r"(a) : "l"(p));
    return a;
}

__device__ __forceinline__ void lds128(unsigned long long& v0, unsigned long long& v1,
                                       unsigned addr) {
    asm volatile("ld.shared.v2.u64 {%0, %1}, [%2];" : "=l"(v0), "=l"(v1) : "r"(addr));
}

__device__ __forceinline__ unsigned long long mul2(unsigned long long a, unsigned long long b) {
    unsigned long long r;
    asm("mul.rn.f32x2 %0, %1, %2;" : "=l"(r) : "l"(a), "l"(b));
    return r;
}

__device__ __forceinline__ unsigned long long fma2(unsigned long long a, unsigned long long b,
                                                   unsigned long long c) {
    unsigned long long r;
    asm("fma.rn.f32x2 %0, %1, %2, %3;" : "=l"(r) : "l"(a), "l"(b), "l"(c));
    return r;
}

__device__ __forceinline__ unsigned long long add2(unsigned long long a, unsigned long long b) {
    unsigned long long r;
    asm("add.rn.f32x2 %0, %1, %2;" : "=l"(r) : "l"(a), "l"(b));
    return r;
}

__device__ __forceinline__ void mbar_init(unsigned mbar, unsigned count) {
    asm volatile("mbarrier.init.shared.b64 [%0], %1;" :: "r"(mbar), "r"(count) : "memory");
}

__device__ __forceinline__ void mbar_expect_tx(unsigned mbar, unsigned bytes) {
    asm volatile("mbarrier.arrive.expect_tx.shared.b64 _, [%0], %1;"
                 :: "r"(mbar), "r"(bytes) : "memory");
}

__device__ __forceinline__ void mbar_wait(unsigned mbar, unsigned parity) {
    asm volatile(
        "{\n\t"
        ".reg .pred P1;\n\t"
        "WAIT_LOOP_%=:\n\t"
        "mbarrier.try_wait.parity.acquire.cta.shared::cta.b64 P1, [%0], %1, 0x989680;\n\t"
        "@P1 bra.uni WAIT_DONE_%=;\n\t"
        "bra.uni WAIT_LOOP_%=;\n\t"
        "WAIT_DONE_%=:\n\t"
        "}"
        :: "r"(mbar), "r"(parity) : "memory");
}

__device__ __forceinline__ void bulk_cp(unsigned sdst, const void* gsrc,
                                        unsigned bytes, unsigned mbar) {
    asm volatile(
        "cp.async.bulk.shared::cta.global.mbarrier::complete_tx::bytes [%0], [%1], %2, [%3];"
        :: "r"(sdst), "l"(gsrc), "r"(bytes), "r"(mbar) : "memory");
}

__device__ __forceinline__ void group_bar(int gid) {
    asm volatile("bar.sync %0, %1;" :: "r"(gid + 1), "r"(128) : "memory");
}

// Leader issues 3 bulk copies (one per source, 4 KB contiguous) into the tile.
__device__ __forceinline__ void issue_stage_bulk(unsigned sdst, long z, unsigned mbar,
                                                 const float* __restrict__ x0,
                                                 const float* __restrict__ x1,
                                                 const float* __restrict__ x2) {
    mbar_expect_tx(mbar, TILE_BYTES);
    bulk_cp(sdst,              x0 + z * SU, SU * 4, mbar);
    bulk_cp(sdst + SU * 4,     x1 + z * SU, SU * 4, mbar);
    bulk_cp(sdst + 2 * SU * 4, x2 + z * SU, SU * 4, mbar);
}

// One path over 4 channels (lane's float4): 3x LDS.128 + packed f32x2 math.
__device__ __forceinline__ void do_path4(unsigned long long& accA, unsigned long long& accB,
                                         unsigned sbase, uint4 m) {
    unsigned long long a0, a1, b0, b1, c0, c1;
    lds128(a0, a1, sbase + m.x);
    lds128(b0, b1, sbase + m.y);
    lds128(c0, c1, sbase + m.z);
    unsigned long long cc;
    asm("mov.b64 %0, {%1, %1};" : "=l"(cc) : "r"(m.w));
    unsigned long long t0 = mul2(a0, b0);
    unsigned long long t1 = mul2(a1, b1);
    t0 = mul2(t0, c0);
    t1 = mul2(t1, c1);
    accA = fma2(t0, cc, accA);
    accB = fma2(t1, cc, accB);
}

__global__ __launch_bounds__(NTHREADS, 2)
void ftp4_kernel(const float* __restrict__ x0,
                 const float* __restrict__ x1,
                 const float* __restrict__ x2,
                 float* __restrict__ out,
                 int Z) {
    extern __shared__ float smem[];   // [GROUPS][2][TILE_FLOATS] then 8 mbarriers

    const int tid = threadIdx.x;
    const int ws = tid >> 5;          // warp slot 0..15
    const int g = ws >> 2;            // group / z-stream 0..3
    const int q = ws & 3;             // j-quarter for this warp
    const int lane = tid & 31;
    const int gt = tid & 127;

    const unsigned smbase = smem_u32(smem);
    const unsigned sb0 = smbase + (unsigned)g * (2 * TILE_BYTES);
    const unsigned sb1 = sb0 + TILE_BYTES;
    const unsigned mbar_base = smbase + (unsigned)(GROUPS * 2 * TILE_BYTES);
    const unsigned mb0 = mbar_base + (unsigned)g * 16;       // buffer 0 mbar
    const unsigned mb1 = mb0 + 8;                             // buffer 1 mbar

    // Init all mbarriers once, then block-wide sync (all threads reach this).
    if (tid < GROUPS * 2) mbar_init(mbar_base + tid * 8, 1);
    __syncthreads();

    const int stream = blockIdx.x * GROUPS + g;
    const int stride = GRID_BLOCKS * GROUPS;            // 1184
    const int nz = (Z > stream) ? ((Z - 1 - stream) / stride + 1) : 0;
    if (nz == 0) return;

    if (gt == 0) issue_stage_bulk(sb0, (long)stream, mb0, x0, x1, x2);

    const int nj = c_prep.qnj[q];

    for (int k = 0; k < nz; k++) {
        const long z = (long)stream + (long)k * stride;
        const int b = k & 1;
        const unsigned scur = b ? sb1 : sb0;

        // Issue next stage into the other buffer (its readers finished at k-1's bar).
        if (k + 1 < nz && gt == 0)
            issue_stage_bulk(b ? sb0 : sb1, z + stride, b ? mb0 : mb1, x0, x1, x2);

        // Wait for current stage (acquire: TMA writes visible to our LDS).
        mbar_wait(b ? mb1 : mb0, (unsigned)((k >> 1) & 1));

        // This warp: its quarter's j-groups over ALL 128 channels; lane owns 4.
        const unsigned sbase = scur + (unsigned)(lane * 16);
        char* ozb = (char*)(out + z * SU + lane * 4);

        for (int t = 0; t < nj; t++) {
            const int joff = c_prep.qjoff[q][t];
            const int pb = c_prep.qstart[q][t];
            const int pe = c_prep.qstart[q][t + 1];
            unsigned long long a0A = 0ull, a0B = 0ull, a1A = 0ull, a1B = 0ull;
            int p = pb;
            for (; p + 1 < pe; p += 2) {
                do_path4(a0A, a0B, sbase, c_prep.meta[p]);
                do_path4(a1A, a1B, sbase, c_prep.meta[p + 1]);
            }
            if (p < pe) do_path4(a0A, a0B, sbase, c_prep.meta[p]);
            unsigned long long accA = add2(a0A, a1A);
            unsigned long long accB = add2(a0B, a1B);

            unsigned r0, r1, r2, r3;
            asm("mov.b64 {%0, %1}, %2;" : "=r"(r0), "=r"(r1) : "l"(accA));
            asm("mov.b64 {%0, %1}, %2;" : "=r"(r2), "=r"(r3) : "l"(accB));
            float4 r;
            r.x = __uint_as_float(r0);
            r.y = __uint_as_float(r1);
            r.z = __uint_as_float(r2);
            r.w = __uint_as_float(r3);
            *(float4*)(ozb + joff) = r;
        }

        group_bar(g);   // all readers of this buffer done before it is re-staged
    }
}

extern "C" void kernel_launch(void* const* d_in, const int* in_sizes, int n_in,
                              void* d_out, int out_size) {
    const float* x0 = (const float*)d_in[0];
    const float* x1 = (const float*)d_in[1];
    const float* x2 = (const float*)d_in[2];
    const float* coeff = (const float*)d_in[3];
    const int*   pidx = (const int*)d_in[4];
    float* out = (float*)d_out;

    const int P = in_sizes[3];            // 64
    const int Z = in_sizes[0] / SU;       // 20000

    prep_kernel<<<1, 32>>>(pidx, coeff, P);

    void* gaddr = nullptr;
    cudaGetSymbolAddress(&gaddr, g_prep);
    cudaMemcpyToSymbolAsync(c_prep, gaddr, sizeof(PrepData), 0,
                            cudaMemcpyDeviceToDevice, 0);

    const size_t smem_bytes = (size_t)GROUPS * 2 * TILE_BYTES + GROUPS * 2 * 8 + 64;

    static bool attr_set = false;
    if (!attr_set) {
        cudaFuncSetAttribute(ftp4_kernel,
                             cudaFuncAttributeMaxDynamicSharedMemorySize,
                             (int)smem_bytes);
        attr_set = true;
    }

    ftp4_kernel<<<GRID_BLOCKS, NTHREADS, smem_bytes>>>(x0, x1, x2, out, Z);
}